// round 9
// baseline (speedup 1.0000x reference)
#include <cuda_runtime.h>
#include <cstdint>
#include <cstddef>

typedef unsigned long long ull;

#define BATCH   32
#define T_STEPS 2048
#define HID     256
#define BT      (BATCH * T_STEPS)         // 65536
#define GCOLS   768                       // [r(256) | z(256) | n(256)] input-side gates
#define BPC     4                         // batches per cluster

// Scratch for input-side projections (static, no cudaMalloc)
__device__ float g_xproj[(size_t)BT * GCOLS];

// ---------------------------------------------------------------------------
// helpers
// ---------------------------------------------------------------------------
__device__ __forceinline__ void ffma2(ull& d, ull a, ull b) {
    asm("fma.rn.f32x2 %0, %1, %2, %0;" : "+l"(d) : "l"(a), "l"(b));
}

__device__ __forceinline__ float tanh_fast(float x) {
    float y;
    asm("tanh.approx.f32 %0, %1;" : "=f"(y) : "f"(x));
    return y;
}

__device__ __forceinline__ float sigmoid_fast(float x) {
    return fmaf(0.5f, tanh_fast(0.5f * x), 0.5f);
}

// plain remote (cluster) 8-byte store — proven primitive on this harness
__device__ __forceinline__ void st_cluster_b64(uint32_t laddr, uint32_t rank, ull v) {
    uint32_t ra;
    asm volatile("mapa.shared::cluster.u32 %0, %1, %2;" : "=r"(ra) : "r"(laddr), "r"(rank));
    asm volatile("st.shared::cluster.b64 [%0], %1;" :: "r"(ra), "l"(v) : "memory");
}

// ---------------------------------------------------------------------------
// Kernel 1: input projection GEMM  (unchanged — measured OK)
// ---------------------------------------------------------------------------
#define PROJ_SMEM_BYTES ((64*256 + 128*260) * 4)

__global__ void __launch_bounds__(128, 1) proj_kernel(
    const float* __restrict__ x,
    const float* __restrict__ W_irz, const float* __restrict__ b_irz,
    const float* __restrict__ W_in,  const float* __restrict__ b_in)
{
    extern __shared__ float smem[];
    float* As = smem;
    float* Bs = smem + 64 * 256;

    const int tid = threadIdx.x;
    const int m0 = blockIdx.x * 64;
    const int n0 = blockIdx.y * 128;

    const float* Wsrc; const float* bsrc;
    if (n0 < 512) { Wsrc = W_irz + (size_t)n0 * 256;         bsrc = b_irz + n0; }
    else          { Wsrc = W_in  + (size_t)(n0 - 512) * 256; bsrc = b_in + (n0 - 512); }

    {
        const float4* xg = (const float4*)(x + (size_t)m0 * 256);
        float4* As4 = (float4*)As;
        #pragma unroll
        for (int it = 0; it < 32; it++) {
            int idx = it * 128 + tid;
            As4[idx] = xg[idx];
        }
        const float4* wg = (const float4*)Wsrc;
        #pragma unroll
        for (int it = 0; it < 64; it++) {
            int idx = it * 128 + tid;
            int n = idx >> 6, k4 = idx & 63;
            *(float4*)(Bs + n * 260 + (k4 << 2)) = wg[idx];
        }
    }
    __syncthreads();

    const int lane = tid & 31, warp = tid >> 5;
    const int cg = lane & 15;
    const int rg2 = lane >> 4;
    const int rglob = warp * 2 + rg2;

    ull acc[64];
    #pragma unroll
    for (int i = 0; i < 64; i++) acc[i] = 0ull;

    const ull* Au = (const ull*)As;
    const ull* Bu = (const ull*)Bs;

    int aoff[8], boff[8];
    #pragma unroll
    for (int i = 0; i < 8; i++) aoff[i] = (rglob + 8 * i) * 128;
    #pragma unroll
    for (int j = 0; j < 8; j++) boff[j] = (cg + 16 * j) * 130;

    #pragma unroll 2
    for (int kk = 0; kk < 128; kk++) {
        ull a2[8], b2[8];
        #pragma unroll
        for (int i = 0; i < 8; i++) a2[i] = Au[aoff[i] + kk];
        #pragma unroll
        for (int j = 0; j < 8; j++) b2[j] = Bu[boff[j] + kk];
        #pragma unroll
        for (int i = 0; i < 8; i++)
            #pragma unroll
            for (int j = 0; j < 8; j++)
                ffma2(acc[i * 8 + j], a2[i], b2[j]);
    }

    float bias[8];
    #pragma unroll
    for (int j = 0; j < 8; j++) bias[j] = bsrc[cg + 16 * j];

    #pragma unroll
    for (int i = 0; i < 8; i++) {
        int m = rglob + 8 * i;
        float* orow = g_xproj + (size_t)(m0 + m) * GCOLS + n0;
        #pragma unroll
        for (int j = 0; j < 8; j++) {
            union { ull u; float f[2]; } v; v.u = acc[i * 8 + j];
            orow[cg + 16 * j] = v.f[0] + v.f[1] + bias[j];
        }
    }
}

// ---------------------------------------------------------------------------
// Kernel 2: persistent GRU, 4 batches per cluster, one cluster barrier per
// 4 batch-steps. Cluster of 4 CTAs; grid 32 (8 clusters); 384 threads.
// Thread map: warp w, lane l. hf = w/6 (k-half), ro = (w%6)*32 + l (gate row).
// All lanes of a warp read the SAME h float4 -> broadcast LDS (N=1).
// Halves combine via gsum[bb][hf][row]; epilogue adds both halves.
// x gate inputs staged in smem xbuf, prefetched by all threads in the
// barrier-wait shadow.
// ---------------------------------------------------------------------------
__global__ void __cluster_dims__(4, 1, 1) __launch_bounds__(384, 1)
gru_kernel(const float* __restrict__ h0,
           const float* __restrict__ W_hrz, const float* __restrict__ b_hrz,
           const float* __restrict__ W_hn,  const float* __restrict__ b_hn,
           float* __restrict__ out, int write_hn)
{
    __shared__ __align__(16) float hbuf[2][BPC][HID];   // 8 KB
    __shared__ float gsum[BPC][2][192];                 // 6 KB
    __shared__ float xbuf[2][BPC][192];                 // 6 KB

    const int tid   = threadIdx.x;
    const int cid   = blockIdx.x >> 2;     // cluster 0..7
    const int rank  = blockIdx.x & 3;
    const int bbase = cid * BPC;           // first batch of this cluster
    const int j0    = rank * 64;           // unit slice of this CTA
    const int wpi   = tid >> 5;            // warp 0..11
    const int lane  = tid & 31;
    const int hf    = (wpi >= 6) ? 1 : 0;  // k-half
    const int ro    = (wpi - hf * 6) * 32 + lane;   // gate row 0..191

    // ---- register-resident weights: row ro, k in [hf*128, hf*128+128) ----
    ull w[64];
    {
        const float* src;
        if (ro < 64)       src = W_hrz + (size_t)(j0 + ro) * 256;
        else if (ro < 128) src = W_hrz + (size_t)(256 + j0 + (ro - 64)) * 256;
        else               src = W_hn  + (size_t)(j0 + (ro - 128)) * 256;
        const ull* ws = (const ull*)src + hf * 64;
        #pragma unroll
        for (int i = 0; i < 64; i++) w[i] = ws[i];
    }

    float bhr = 0.f, bhz = 0.f, bhn = 0.f;
    if (tid < 64) {
        bhr = b_hrz[j0 + tid];
        bhz = b_hrz[256 + j0 + tid];
        bhn = b_hn[j0 + tid];
    }
    if (tid < HID) {
        #pragma unroll
        for (int bb = 0; bb < BPC; bb++)
            hbuf[0][bb][tid] = h0[(size_t)(bbase + bb) * HID + tid];
    }
    // prefill xbuf[0] with t=0 gate inputs: 4*192 = 768 values, 2 per thread
    {
        #pragma unroll
        for (int s = 0; s < 2; s++) {
            int v = tid + s * 384;
            int bb = v / 192, rr = v % 192;
            int g = rr >> 6, u = rr & 63;
            xbuf[0][bb][rr] =
                g_xproj[(size_t)(bbase + bb) * T_STEPS * GCOLS + (g << 8) + j0 + u];
        }
    }
    __syncthreads();
    asm volatile("barrier.cluster.arrive.aligned;" ::: "memory");
    asm volatile("barrier.cluster.wait.aligned;"  ::: "memory");

    const uint32_t hb0 = (uint32_t)__cvta_generic_to_shared(&hbuf[0][0][0]);

    for (int t = 0; t < T_STEPS; t++) {
        const int par = t & 1;

        // ---- 4 matvecs (broadcast LDS: warp-uniform h addresses) ----
        #pragma unroll
        for (int bb = 0; bb < BPC; bb++) {
            ull acc0 = 0ull, acc1 = 0ull;
            const float4* h4 = (const float4*)&hbuf[par][bb][hf << 7];
            #pragma unroll
            for (int i = 0; i < 32; i++) {
                union { float4 f; ull u[2]; } hv;
                hv.f = h4[i];
                ffma2(acc0, w[2 * i],     hv.u[0]);
                ffma2(acc1, w[2 * i + 1], hv.u[1]);
            }
            union { ull u; float f[2]; } ua, ub;
            ua.u = acc0; ub.u = acc1;
            gsum[bb][hf][ro] = (ua.f[0] + ua.f[1]) + (ub.f[0] + ub.f[1]);
        }
        __syncthreads();

        // ---- epilogue: 64 threads (warps 0,1) finalize all 4 batches ----
        float hnew[BPC];
        if (tid < 64) {
            const int j = tid;
            #pragma unroll
            for (int bb = 0; bb < BPC; bb++) {
                float sr = gsum[bb][0][j]       + gsum[bb][1][j];
                float sz = gsum[bb][0][64 + j]  + gsum[bb][1][64 + j];
                float sn = gsum[bb][0][128 + j] + gsum[bb][1][128 + j];
                float r = sigmoid_fast(sr + bhr + xbuf[par][bb][j]);
                float z = sigmoid_fast(sz + bhz + xbuf[par][bb][64 + j]);
                float n = tanh_fast(fmaf(r, sn + bhn, xbuf[par][bb][128 + j]));
                float hold = hbuf[par][bb][j0 + j];
                hnew[bb] = fmaf(z, hold - n, n);      // (1-z)*n + z*h

                // pair-pack; even tid -> ranks 0,1 ; odd tid -> ranks 2,3
                float hp = __shfl_xor_sync(0xffffffffu, hnew[bb], 1);
                union { float f[2]; ull u; } pk;
                if ((j & 1) == 0) { pk.f[0] = hnew[bb]; pk.f[1] = hp; }
                else              { pk.f[0] = hp;       pk.f[1] = hnew[bb]; }
                uint32_t laddr = hb0 +
                    (uint32_t)((((par ^ 1) * BPC + bb) * HID) + j0 + (j & ~1)) * 4u;
                uint32_t r0 = (j & 1) ? 2u : 0u;
                st_cluster_b64(laddr, r0,      pk.u);
                st_cluster_b64(laddr, r0 + 1u, pk.u);
            }
        }

        // arrive releases the remote sends; DRAM traffic below runs in the shadow
        asm volatile("barrier.cluster.arrive.aligned;" ::: "memory");

        if (tid < 64) {
            #pragma unroll
            for (int bb = 0; bb < BPC; bb++) {
                out[(size_t)(bbase + bb) * T_STEPS * HID + (size_t)t * HID + j0 + tid]
                    = hnew[bb];
                if (write_hn && t == T_STEPS - 1)
                    out[(size_t)BATCH * T_STEPS * HID +
                        (size_t)(bbase + bb) * HID + j0 + tid] = hnew[bb];
            }
        }
        // prefetch next step's x into xbuf[par^1] (all 384 threads, 2 each)
        {
            const int tn = (t + 1 < T_STEPS) ? (t + 1) : (T_STEPS - 1);
            #pragma unroll
            for (int s = 0; s < 2; s++) {
                int v = tid + s * 384;
                int bb = v / 192, rr = v % 192;
                int g = rr >> 6, u = rr & 63;
                xbuf[par ^ 1][bb][rr] =
                    g_xproj[(size_t)(bbase + bb) * T_STEPS * GCOLS +
                            (size_t)tn * GCOLS + (g << 8) + j0 + u];
            }
        }

        asm volatile("barrier.cluster.wait.aligned;"  ::: "memory");
    }
}

// ---------------------------------------------------------------------------
// launch
// ---------------------------------------------------------------------------
extern "C" void kernel_launch(void* const* d_in, const int* in_sizes, int n_in,
                              void* d_out, int out_size)
{
    (void)in_sizes; (void)n_in;
    const float* x     = (const float*)d_in[0];
    const float* h0    = (const float*)d_in[1];
    const float* W_irz = (const float*)d_in[2];
    const float* b_irz = (const float*)d_in[3];
    const float* W_hrz = (const float*)d_in[4];
    const float* b_hrz = (const float*)d_in[5];
    const float* W_in  = (const float*)d_in[6];
    const float* b_in  = (const float*)d_in[7];
    const float* W_hn  = (const float*)d_in[8];
    const float* b_hn  = (const float*)d_in[9];
    float* out = (float*)d_out;

    cudaFuncSetAttribute(proj_kernel, cudaFuncAttributeMaxDynamicSharedMemorySize,
                         PROJ_SMEM_BYTES);
    cudaFuncSetAttribute(gru_kernel, cudaFuncAttributeNonPortableClusterSizeAllowed, 1);

    proj_kernel<<<dim3(BT / 64, GCOLS / 128, 1), 128, PROJ_SMEM_BYTES>>>(
        x, W_irz, b_irz, W_in, b_in);

    const long long need_hn = (long long)BATCH * T_STEPS * HID + (long long)BATCH * HID;
    int write_hn = ((long long)out_size >= need_hn) ? 1 : 0;
    gru_kernel<<<(BATCH / BPC) * 4, 384>>>(h0, W_hrz, b_hrz, W_hn, b_hn, out, write_hn);
}